// round 10
// baseline (speedup 1.0000x reference)
#include <cuda_runtime.h>
#include <stdint.h>

// Per-target-row fused table, 12 floats per row (48B stride -> conflict-free LDS.128):
//   [ st0..st4 , w0..w4 , pad, pad ]
// st[t][j] = 0.025 + 0.875*(j==t)   (smoothed-target weights; CE = lse - x.st)
// w[t][j]  = T[t][j] in {0,0.5,1,2} (transition penalty weights)

__global__ void zero_out_kernel(float* out) {
    if (threadIdx.x == 0) out[0] = 0.0f;
}

__device__ __forceinline__ float row_loss(const float* __restrict__ wrow,
                                          float a, float b, float c, float d, float e) {
    // exps (inputs ~ N(0,1): no max-shift needed; overflow at |x|~88)
    float e0 = __expf(a);
    float e1 = __expf(b);
    float e2 = __expf(c);
    float e3 = __expf(d);
    float e4 = __expf(e);
    float S  = ((e0 + e1) + (e2 + e3)) + e4;

    float4 s0 = *reinterpret_cast<const float4*>(wrow);       // st0..st3
    float4 s1 = *reinterpret_cast<const float4*>(wrow + 4);   // st4, w0, w1, w2
    float4 s2 = *reinterpret_cast<const float4*>(wrow + 8);   // w3, w4, pad, pad

    // smoothed-target dot: sum_j x_j * st_j
    float std_ = a * s0.x;
    std_ = fmaf(b, s0.y, std_);
    std_ = fmaf(c, s0.z, std_);
    std_ = fmaf(d, s0.w, std_);
    std_ = fmaf(e, s1.x, std_);

    // transition dot: sum_j e_j * w_j
    float wd = e0 * s1.y;
    wd = fmaf(e1, s1.z, wd);
    wd = fmaf(e2, s1.w, wd);
    wd = fmaf(e3, s2.x, wd);
    wd = fmaf(e4, s2.y, wd);

    float lse = __logf(S);
    return (lse - std_) + 0.1f * __fdividef(wd, S);
}

__global__ __launch_bounds__(256, 6)
void bloom_loss_kernel(const float* __restrict__ x,
                       const int*   __restrict__ tgt,
                       float* __restrict__ out,
                       int B, float invB) {
    __shared__ float wtab[5 * 12];
    __shared__ float warp_sums[8];

    // build fused table (60 entries)
    if (threadIdx.x < 60) {
        int t = threadIdx.x / 12;
        int col = threadIdx.x % 12;
        float v = 0.0f;
        if (col < 5) {
            v = (col == t) ? 0.9f : 0.025f;
        } else if (col < 10) {
            int j = col - 5;
            int dd = t - j; if (dd < 0) dd = -dd;
            v = (dd == 0) ? 0.0f : (dd == 1) ? 0.5f : (dd == 2) ? 1.0f : 2.0f;
        }
        wtab[threadIdx.x] = v;
    }
    __syncthreads();

    int g = blockIdx.x * blockDim.x + threadIdx.x;   // group of 4 rows
    int base = g * 4;
    float acc = 0.0f;

    if (base + 3 < B) {
        const float4* xv = reinterpret_cast<const float4*>(x) + (size_t)5 * g;
        float4 v0 = xv[0];
        float4 v1 = xv[1];
        float4 v2 = xv[2];
        float4 v3 = xv[3];
        float4 v4 = xv[4];
        int4 t4 = reinterpret_cast<const int4*>(tgt)[g];

        acc += row_loss(wtab + t4.x * 12, v0.x, v0.y, v0.z, v0.w, v1.x);
        acc += row_loss(wtab + t4.y * 12, v1.y, v1.z, v1.w, v2.x, v2.y);
        acc += row_loss(wtab + t4.z * 12, v2.z, v2.w, v3.x, v3.y, v3.z);
        acc += row_loss(wtab + t4.w * 12, v3.w, v4.x, v4.y, v4.z, v4.w);
    } else if (base < B) {
        for (int r = base; r < B; r++) {
            const float* p = x + (size_t)r * 5;
            acc += row_loss(wtab + tgt[r] * 12, p[0], p[1], p[2], p[3], p[4]);
        }
    }

    // warp reduce
    #pragma unroll
    for (int off = 16; off > 0; off >>= 1)
        acc += __shfl_xor_sync(0xFFFFFFFFu, acc, off);

    int lane = threadIdx.x & 31;
    int wid  = threadIdx.x >> 5;
    if (lane == 0) warp_sums[wid] = acc;
    __syncthreads();

    if (wid == 0) {
        float s = (lane < 8) ? warp_sums[lane] : 0.0f;
        #pragma unroll
        for (int off = 4; off > 0; off >>= 1)
            s += __shfl_xor_sync(0xFFFFFFFFu, s, off);
        if (lane == 0) atomicAdd(out, s * invB);
    }
}

extern "C" void kernel_launch(void* const* d_in, const int* in_sizes, int n_in,
                              void* d_out, int out_size) {
    const float* x   = (const float*)d_in[0];
    const int*   tgt = (const int*)d_in[1];
    float* out = (float*)d_out;
    int B = in_sizes[1];   // rows == targets

    zero_out_kernel<<<1, 32>>>(out);

    int groups = (B + 3) / 4;
    int blocks = (groups + 255) / 256;
    bloom_loss_kernel<<<blocks, 256>>>(x, tgt, out, B, 1.0f / (float)B);
}

// round 14
// speedup vs baseline: 1.2250x; 1.2250x over previous
#include <cuda_runtime.h>
#include <stdint.h>

// Transition weights T[t][j] depend only on o = j - t + 4 in [0,8]:
// w = {2, 2, 1, 0.5, 0, 0.5, 1, 2, 2}  — all powers of two (or 0).
// Encoded as fp32 EXPONENT bytes: 2->0x80, 1->0x7F, 0.5->0x7E, 0->0x00.
#define WPA 0x7E7F8080u   // bytes 0-3
#define WPB 0x807F7E00u   // bytes 4-7
#define WPC 0x00000080u   // byte 8

__global__ void zero_out_kernel(float* out) {
    if (threadIdx.x == 0) out[0] = 0.0f;
}

__device__ __forceinline__ float row_loss(float a, float b, float c, float d, float e, int t) {
    // inputs ~ N(0,1): no max-subtraction needed (fp32 exp overflows at |x|~88)
    float e0 = __expf(a);
    float e1 = __expf(b);
    float e2 = __expf(c);
    float e3 = __expf(d);
    float e4 = __expf(e);
    float S  = ((e0 + e1) + (e2 + e3)) + e4;

    float sumx = ((a + b) + (c + d)) + e;
    float xt = (t < 2) ? (t == 0 ? a : b) : (t == 2 ? c : (t == 3 ? d : e));

    // this t's weight-exponent bytes live at diagonal offsets (4-t)..(8-t)
    unsigned sh = 32u - 8u * (unsigned)t;
    unsigned rl = __funnelshift_rc(WPA, WPB, sh);   // exponent bytes for j=0..3
    unsigned rh = __funnelshift_rc(WPB, WPC, sh);   // byte0 = j=4

    float w0 = __uint_as_float((rl << 23) & 0x7F800000u);
    float w1 = __uint_as_float((rl << 15) & 0x7F800000u);
    float w2 = __uint_as_float((rl <<  7) & 0x7F800000u);
    float w3 = __uint_as_float((rl >>  1) & 0x7F800000u);
    float w4 = __uint_as_float((rh << 23) & 0x7F800000u);

    float numer =      e0 * w0;
    numer = fmaf(e1, w1, numer);
    numer = fmaf(e2, w2, numer);
    numer = fmaf(e3, w3, numer);
    numer = fmaf(e4, w4, numer);

    float lse = __logf(S);
    // CE = lse - (0.025*sum(x) + 0.875*x_t);  penalty scaled by TPEN=0.1
    float ce = lse - fmaf(0.025f, sumx, 0.875f * xt);
    return fmaf(0.1f, __fdividef(numer, S), ce);
}

// Persistent main kernel: grid-stride over full groups of 4 rows.
__global__ __launch_bounds__(256, 6)
void bloom_loss_kernel(const float* __restrict__ x,
                       const int*   __restrict__ tgt,
                       float* __restrict__ out,
                       int ngroups, int stride, float invB) {
    float acc = 0.0f;

    for (int g = blockIdx.x * blockDim.x + threadIdx.x; g < ngroups; g += stride) {
        const float4* xv = reinterpret_cast<const float4*>(x) + (size_t)5 * g;
        float4 v0 = xv[0];
        float4 v1 = xv[1];
        float4 v2 = xv[2];
        float4 v3 = xv[3];
        float4 v4 = xv[4];
        int4 t4 = reinterpret_cast<const int4*>(tgt)[g];

        acc += row_loss(v0.x, v0.y, v0.z, v0.w, v1.x, t4.x);
        acc += row_loss(v1.y, v1.z, v1.w, v2.x, v2.y, t4.y);
        acc += row_loss(v2.z, v2.w, v3.x, v3.y, v3.z, t4.z);
        acc += row_loss(v3.w, v4.x, v4.y, v4.z, v4.w, t4.w);
    }

    // warp reduce
    #pragma unroll
    for (int off = 16; off > 0; off >>= 1)
        acc += __shfl_xor_sync(0xFFFFFFFFu, acc, off);

    __shared__ float warp_sums[8];
    int lane = threadIdx.x & 31;
    int wid  = threadIdx.x >> 5;
    if (lane == 0) warp_sums[wid] = acc;
    __syncthreads();

    if (wid == 0) {
        float s = (lane < 8) ? warp_sums[lane] : 0.0f;
        #pragma unroll
        for (int off = 4; off > 0; off >>= 1)
            s += __shfl_xor_sync(0xFFFFFFFFu, s, off);
        if (lane == 0) atomicAdd(out, s * invB);
    }
}

// Tail rows (B % 4 != 0): tiny separate kernel, zero blocks of work when B%4==0.
__global__ void bloom_tail_kernel(const float* __restrict__ x,
                                  const int*   __restrict__ tgt,
                                  float* __restrict__ out,
                                  int start, int B, float invB) {
    if (threadIdx.x == 0 && blockIdx.x == 0) {
        float acc = 0.0f;
        for (int r = start; r < B; r++) {
            const float* p = x + (size_t)r * 5;
            acc += row_loss(p[0], p[1], p[2], p[3], p[4], tgt[r]);
        }
        atomicAdd(out, acc * invB);
    }
}

extern "C" void kernel_launch(void* const* d_in, const int* in_sizes, int n_in,
                              void* d_out, int out_size) {
    const float* x   = (const float*)d_in[0];
    const int*   tgt = (const int*)d_in[1];
    float* out = (float*)d_out;
    int B = in_sizes[1];   // rows == targets
    float invB = 1.0f / (float)B;

    zero_out_kernel<<<1, 32>>>(out);

    int ngroups = B >> 2;
    // one wave on GB300: 152 SMs x 6 blocks/SM, clamped to available work
    int blocks = 152 * 6;
    int maxb = (ngroups + 255) / 256;
    if (blocks > maxb) blocks = maxb;
    if (blocks < 1) blocks = 1;
    int stride = blocks * 256;

    bloom_loss_kernel<<<blocks, 256>>>(x, tgt, out, ngroups, stride, invB);

    if (B & 3)
        bloom_tail_kernel<<<1, 32>>>(x, tgt, out, ngroups << 2, B, invB);
}